// round 10
// baseline (speedup 1.0000x reference)
#include <cuda_runtime.h>
#include <stdint.h>
#include <math.h>

// ---------------------------------------------------------------------------
// Problem constants
// ---------------------------------------------------------------------------
#define NB      16       // batch
#define NCLS    80       // classes
#define NANCH   25200    // 80*80*3 + 40*40*3 + 20*20*3
#define TOPK    128      // NMS_TOPK
#define MAXOUT  100
#define SCORE_THR 0.25f
#define IOU_THR   0.45f

#define K1_CELLS   16    // cells per block (divides 6400, 1600, 400, and 8400)
#define K1_THREADS 128
#define CAND_MAX   2048
#define CAP        16384 // per-(b,class) candidate capacity (mean ~9.1k, sigma ~80)

// ---------------------------------------------------------------------------
// Scratch (static __device__ arrays — no allocation allowed)
// ---------------------------------------------------------------------------
__device__ unsigned long long g_cand[(size_t)NB * NCLS * CAP];  // 168 MB candidate keys
__device__ unsigned g_ccnt[NB * NCLS];                          // per-task candidate counts
__device__ float g_boxes[(size_t)NB * NANCH * 4];               // (B, N, 4)
__device__ float g_cls_scores[NB * NCLS * MAXOUT];              // per-class NMS scores (-1 = invalid)
__device__ float g_cls_boxes[NB * NCLS * MAXOUT * 4];           // per-class NMS boxes

__constant__ float c_anchor_w[9] = {10.f, 16.f, 33.f, 30.f, 62.f, 59.f, 116.f, 156.f, 373.f};
__constant__ float c_anchor_h[9] = {13.f, 30.f, 23.f, 61.f, 45.f, 119.f, 90.f, 198.f, 326.f};

__device__ __forceinline__ float sigm(float x) {
    return 1.0f / (1.0f + expf(-x));
}

// map any float to a monotone unsigned key
__device__ __forceinline__ unsigned fkeymap(float f) {
    unsigned u = __float_as_uint(f);
    return (u & 0x80000000u) ? ~u : (u | 0x80000000u);
}

// ---------------------------------------------------------------------------
// K0: reset per-task candidate counters (graph replay safety)
// ---------------------------------------------------------------------------
__global__ void reset_kernel()
{
    int i = blockIdx.x * 256 + threadIdx.x;
    if (i < NB * NCLS) g_ccnt[i] = 0;
}

// ---------------------------------------------------------------------------
// K1: decode + candidate extraction (no dense score matrix).
// Block = 128 threads handles 16 cells (48 anchors, 4080 input floats).
// Grid = NB*8400/16 = 8400 blocks.
// ---------------------------------------------------------------------------
__global__ __launch_bounds__(K1_THREADS) void decode_kernel(
    const float* __restrict__ p3, const float* __restrict__ p4, const float* __restrict__ p5)
{
    __shared__ float s_in[K1_CELLS * 255];     // 16320 B, contiguous input slab
    __shared__ float s_obj[K1_CELLS * 3];

    const int tid = threadIdx.x;
    const int lane = tid & 31;
    int cell0 = blockIdx.x * K1_CELLS;         // global cell index (B x 8400 cells)
    int b  = cell0 / 8400;
    int r0 = cell0 - b * 8400;                 // image-local cell

    const float* src; int W; float strd; int abase; int n0; int hw0;
    if (r0 < 6400)      { hw0 = r0;        W = 80; strd = 8.f;  abase = 0; src = p3 + ((size_t)b * 6400 + hw0) * 255; n0 = hw0 * 3; }
    else if (r0 < 8000) { hw0 = r0 - 6400; W = 40; strd = 16.f; abase = 3; src = p4 + ((size_t)b * 1600 + hw0) * 255; n0 = 19200 + hw0 * 3; }
    else                { hw0 = r0 - 8000; W = 20; strd = 32.f; abase = 6; src = p5 + ((size_t)b *  400 + hw0) * 255; n0 = 24000 + hw0 * 3; }

    // stage: fully coalesced contiguous copy
    #pragma unroll 4
    for (int i = tid; i < K1_CELLS * 255; i += K1_THREADS) s_in[i] = src[i];
    __syncthreads();

    // decode 48 anchors (threads 0..47); anchor j -> shared offset 85*j
    if (tid < K1_CELLS * 3) {
        int cl = tid / 3;
        int a  = tid - cl * 3;
        int hw = hw0 + cl;
        int y  = hw / W;
        int x  = hw - y * W;
        const float* q = s_in + tid * 85;      // cl*255 + a*85 == 85*tid

        float cx = (sigm(q[0]) + (float)x) * strd;
        float cy = (sigm(q[1]) + (float)y) * strd;
        float w  = expf(q[2]) * c_anchor_w[abase + a];
        float h  = expf(q[3]) * c_anchor_h[abase + a];

        float* bo = g_boxes + ((size_t)b * NANCH + n0 + tid) * 4;
        bo[0] = cx - w * 0.5f;
        bo[1] = cy - h * 0.5f;
        bo[2] = cx + w * 0.5f;
        bo[3] = cy + h * 0.5f;

        s_obj[tid] = sigm(q[4]);
    }
    __syncthreads();

    // scores: 48 anchors x 80 classes; warp-aggregated candidate append per class
    const int NA = K1_CELLS * 3;               // 48
    #pragma unroll 3
    for (int w = 0; w < (NA * NCLS) / K1_THREADS; ++w) {   // 30 iterations
        int idx = w * K1_THREADS + tid;
        int c = idx / NA;                      // warp spans at most 2 classes
        int j = idx - c * NA;
        float v = s_obj[j] * sigm(s_in[j * 85 + 5 + c]);   // 85-word stride: conflict-free
        bool pass = v > SCORE_THR;

        unsigned same    = __match_any_sync(0xFFFFFFFFu, c);
        unsigned actSame = __ballot_sync(0xFFFFFFFFu, pass) & same;
        int leader = __ffs(actSame) - 1;                   // own bit set whenever pass
        unsigned base = 0;
        if (pass && lane == leader)
            base = atomicAdd(&g_ccnt[b * NCLS + c], __popc(actSame));
        base = __shfl_sync(0xFFFFFFFFu, base, leader >= 0 ? leader : 0);
        if (pass) {
            unsigned p = base + __popc(actSame & ((1u << lane) - 1u));
            if (p < CAP) {
                int n = n0 + j;
                g_cand[((size_t)(b * NCLS + c)) * CAP + p] =
                    ((unsigned long long)__float_as_uint(v) << 32) | (unsigned)(0x00FFFFFF - n);
            }
        }
    }
}

// ---------------------------------------------------------------------------
// K2: per (b, class): exact top-128 via histogram threshold over the compact
// candidate list + small sort + NMS. one block of 256 threads per task.
// ---------------------------------------------------------------------------
__global__ __launch_bounds__(256) void topk_nms_kernel()
{
    const int task = blockIdx.x;
    const int b = task / NCLS;
    const int tid = threadIdx.x;

    const unsigned long long* __restrict__ cand = g_cand + (size_t)task * CAP;
    const int cnt = (int)min(g_ccnt[task], (unsigned)CAP);

    __shared__ unsigned long long s_cand[CAND_MAX];        // 16 KB; aliased as hist in pass A
    unsigned* hist = (unsigned*)s_cand;                    // 4096 buckets
    __shared__ unsigned s_csum[256];
    __shared__ unsigned s_T, s_cnt;

    // --- pass A: histogram of score bits (scores in (0.25, 1) span exactly 2^24 codes) ---
    for (int i = tid; i < 4096; i += 256) hist[i] = 0;
    __syncthreads();

    // two keys per iteration to halve LDG issue count
    for (int i = tid * 2; i < cnt; i += 512) {
        unsigned long long k0 = cand[i];
        unsigned bk0 = min(((unsigned)(k0 >> 32) - 0x3E800000u) >> 12, 4095u);
        atomicAdd(&hist[bk0], 1u);
        if (i + 1 < cnt) {
            unsigned long long k1 = cand[i + 1];
            unsigned bk1 = min(((unsigned)(k1 >> 32) - 0x3E800000u) >> 12, 4095u);
            atomicAdd(&hist[bk1], 1u);
        }
    }
    __syncthreads();

    // --- per-thread chunk sums (16 buckets each) ---
    unsigned sum = 0;
    #pragma unroll
    for (int k = 0; k < 16; ++k) sum += hist[tid * 16 + k];
    s_csum[tid] = sum;
    __syncthreads();

    // --- thread 0: find threshold bucket T (suffix count first >= 128) ---
    if (tid == 0) {
        unsigned acc = 0;
        int ch;
        for (ch = 255; ch >= 0; --ch) {
            if (acc + s_csum[ch] >= TOPK) break;
            acc += s_csum[ch];
        }
        unsigned T = 0;
        if (ch >= 0) {
            for (int q = ch * 16 + 15; q >= ch * 16; --q) {
                acc += hist[q];
                if (acc >= TOPK) { T = (unsigned)q; break; }
            }
        }
        s_T = T;
        s_cnt = 0;
    }
    __syncthreads();

    // --- pass B: collect candidate keys with bucket >= T (overwrites hist region) ---
    unsigned T = s_T;
    for (int i = tid * 2; i < cnt; i += 512) {
        unsigned long long k0 = cand[i];
        unsigned bk0 = min(((unsigned)(k0 >> 32) - 0x3E800000u) >> 12, 4095u);
        if (bk0 >= T) {
            unsigned p = atomicAdd(&s_cnt, 1u);
            if (p < CAND_MAX) s_cand[p] = k0;
        }
        if (i + 1 < cnt) {
            unsigned long long k1 = cand[i + 1];
            unsigned bk1 = min(((unsigned)(k1 >> 32) - 0x3E800000u) >> 12, 4095u);
            if (bk1 >= T) {
                unsigned p = atomicAdd(&s_cnt, 1u);
                if (p < CAND_MAX) s_cand[p] = k1;
            }
        }
    }
    __syncthreads();

    int ccnt = (int)min(s_cnt, (unsigned)CAND_MAX);
    int P = TOPK;
    while (P < ccnt) P <<= 1;                  // power-of-two sort size >= max(ccnt, 128)
    for (int i = ccnt + tid; i < P; i += 256) s_cand[i] = 0ull;
    __syncthreads();

    // --- bitonic sort P keys descending (P typically 128 or 256) ---
    for (int k = 2; k <= P; k <<= 1) {
        for (int j = k >> 1; j > 0; j >>= 1) {
            for (int i = tid; i < P; i += 256) {
                int l = i ^ j;
                if (l > i) {
                    unsigned long long a  = s_cand[i];
                    unsigned long long bb = s_cand[l];
                    bool desc = ((i & k) == 0);
                    if ((a < bb) == desc) { s_cand[i] = bb; s_cand[l] = a; }
                }
            }
            __syncthreads();
        }
    }

    // --- gather top-128 candidates ---
    __shared__ float s_bx1[TOPK], s_by1[TOPK], s_bx2[TOPK], s_by2[TOPK];
    __shared__ float s_area[TOPK], s_score[TOPK];
    __shared__ unsigned s_sup[TOPK][4];
    __shared__ unsigned s_keep[4];
    __shared__ unsigned s_vball[4];

    if (tid < MAXOUT) g_cls_scores[task * MAXOUT + tid] = -1.0f;   // default invalid

    if (tid < TOPK) {
        unsigned long long key = s_cand[tid];
        float s = __uint_as_float((unsigned)(key >> 32));
        int n = 0x00FFFFFF - (int)(unsigned)(key & 0xFFFFFFFFull);
        if (!(s > 0.f)) n = 0;     // padding slot: any in-range box, never used
        s_score[tid] = s;
        const float* bp = g_boxes + ((size_t)b * NANCH + n) * 4;
        float x1 = bp[0], y1 = bp[1], x2 = bp[2], y2 = bp[3];
        s_bx1[tid] = x1; s_by1[tid] = y1; s_bx2[tid] = x2; s_by2[tid] = y2;
        s_area[tid] = (x2 - x1) * (y2 - y1);
    }
    __syncthreads();

    // --- suppression bitmask: s_sup[i][w] bit t set iff j=32w+t > i and iou(i,j) > thr ---
    for (int wi = tid; wi < TOPK * 4; wi += 256) {
        int i = wi >> 2;
        int w = wi & 3;
        float ax1 = s_bx1[i], ay1 = s_by1[i], ax2 = s_bx2[i], ay2 = s_by2[i], aa = s_area[i];
        unsigned m = 0;
        #pragma unroll 4
        for (int tt = 0; tt < 32; ++tt) {
            int j = (w << 5) + tt;
            if (j > i) {
                float iw = fmaxf(fminf(ax2, s_bx2[j]) - fmaxf(ax1, s_bx1[j]), 0.f);
                float ih = fmaxf(fminf(ay2, s_by2[j]) - fmaxf(ay1, s_by1[j]), 0.f);
                float inter = iw * ih;
                float iou = inter / (aa + s_area[j] - inter + 1e-9f);
                if (iou > IOU_THR) m |= (1u << tt);
            }
        }
        s_sup[i][w] = m;
    }
    __syncthreads();

    // --- sequential NMS scan (the lax.scan) on 128-bit bitmask ---
    if (tid == 0) {
        unsigned k0 = 0xFFFFFFFFu, k1 = 0xFFFFFFFFu, k2 = 0xFFFFFFFFu, k3 = 0xFFFFFFFFu;
        for (int i = 0; i < TOPK; ++i) {
            unsigned kw = (i < 32) ? k0 : (i < 64) ? k1 : (i < 96) ? k2 : k3;
            if (((kw >> (i & 31)) & 1u) && (s_score[i] > 0.f)) {
                k0 &= ~s_sup[i][0]; k1 &= ~s_sup[i][1]; k2 &= ~s_sup[i][2]; k3 &= ~s_sup[i][3];
            }
        }
        s_keep[0] = k0; s_keep[1] = k1; s_keep[2] = k2; s_keep[3] = k3;
    }
    __syncthreads();

    // --- compact valid survivors in order -> per-class top-100 ---
    bool valid = false;
    if (tid < TOPK) {
        valid = (((s_keep[tid >> 5] >> (tid & 31)) & 1u) != 0) && (s_score[tid] > 0.f);
        unsigned bal = __ballot_sync(0xFFFFFFFFu, valid);
        if ((tid & 31) == 0) s_vball[tid >> 5] = bal;
    }
    __syncthreads();

    if (tid < TOPK && valid) {
        int w = tid >> 5;
        int pos = __popc(s_vball[w] & ((1u << (tid & 31)) - 1u));
        #pragma unroll
        for (int q = 0; q < 4; ++q) if (q < w) pos += __popc(s_vball[q]);
        if (pos < MAXOUT) {
            size_t o = (size_t)task * MAXOUT + pos;
            g_cls_scores[o] = s_score[tid];
            float* ob = g_cls_boxes + o * 4;
            ob[0] = s_bx1[tid]; ob[1] = s_by1[tid]; ob[2] = s_bx2[tid]; ob[3] = s_by2[tid];
        }
    }
}

// ---------------------------------------------------------------------------
// K3: per-image top-100 over 80 sorted per-class lists (exact streaming merge)
// one warp per image
// ---------------------------------------------------------------------------
__global__ __launch_bounds__(32) void final_kernel(float* __restrict__ out)
{
    int b = blockIdx.x;
    int lane = threadIdx.x;

    int ptrq[3];
    unsigned long long hk[3];
    #pragma unroll
    for (int q = 0; q < 3; ++q) {
        int c = lane + 32 * q;
        ptrq[q] = 0;
        if (c < NCLS) {
            float s = g_cls_scores[(b * NCLS + c) * MAXOUT];
            unsigned flat = (unsigned)(c * MAXOUT);
            hk[q] = ((unsigned long long)fkeymap(s) << 32) | (unsigned)(0xFFFFu - flat);
        } else hk[q] = 0ull;
    }

    int nval = 0;
    for (int rr = 0; rr < MAXOUT; ++rr) {
        unsigned long long best = hk[0]; int bq = 0;
        if (hk[1] > best) { best = hk[1]; bq = 1; }
        if (hk[2] > best) { best = hk[2]; bq = 2; }

        unsigned long long gmax = best;
        #pragma unroll
        for (int off = 16; off > 0; off >>= 1) {
            unsigned long long o = __shfl_xor_sync(0xFFFFFFFFu, gmax, off);
            if (o > gmax) gmax = o;
        }
        bool val = ((unsigned)(gmax >> 32)) > 0x80000000u;   // score > 0

        if (best == gmax) {   // unique winner (flat index embedded in key)
            int c = lane + 32 * bq;
            int k = ptrq[bq];
            float* ob = out + ((size_t)b * MAXOUT + rr) * 4;
            if (val) {
                size_t o = (size_t)(b * NCLS + c) * MAXOUT + k;
                float s = g_cls_scores[o];
                const float* bp = g_cls_boxes + o * 4;
                ob[0] = bp[0]; ob[1] = bp[1]; ob[2] = bp[2]; ob[3] = bp[3];
                out[NB * MAXOUT * 4 + b * MAXOUT + rr] = s;
                out[NB * MAXOUT * 5 + b * MAXOUT + rr] = (float)c;
            } else {
                ob[0] = 0.f; ob[1] = 0.f; ob[2] = 0.f; ob[3] = 0.f;
                out[NB * MAXOUT * 4 + b * MAXOUT + rr] = 0.f;
                out[NB * MAXOUT * 5 + b * MAXOUT + rr] = 0.f;
            }
            k++;
            ptrq[bq] = k;
            if (k < MAXOUT && c < NCLS) {
                float s = g_cls_scores[(b * NCLS + c) * MAXOUT + k];
                unsigned flat = (unsigned)(c * MAXOUT + k);
                hk[bq] = ((unsigned long long)fkeymap(s) << 32) | (unsigned)(0xFFFFu - flat);
            } else hk[bq] = 0ull;
        }
        nval += val ? 1 : 0;
    }
    if (lane == 0) out[NB * MAXOUT * 6 + b] = (float)nval;
}

// ---------------------------------------------------------------------------
// Entry point
// ---------------------------------------------------------------------------
extern "C" void kernel_launch(void* const* d_in, const int* in_sizes, int n_in,
                              void* d_out, int out_size)
{
    // identify inputs by element count (robust to ordering)
    const float* p3 = nullptr; const float* p4 = nullptr; const float* p5 = nullptr;
    for (int i = 0; i < n_in; ++i) {
        if      (in_sizes[i] == 16 * 80 * 80 * 255) p3 = (const float*)d_in[i];
        else if (in_sizes[i] == 16 * 40 * 40 * 255) p4 = (const float*)d_in[i];
        else if (in_sizes[i] == 16 * 20 * 20 * 255) p5 = (const float*)d_in[i];
    }
    float* out = (float*)d_out;

    reset_kernel<<<(NB * NCLS + 255) / 256, 256>>>();
    decode_kernel<<<(NB * 8400) / K1_CELLS, K1_THREADS>>>(p3, p4, p5);  // 8400 blocks
    topk_nms_kernel<<<NB * NCLS, 256>>>();                              // 1280 blocks
    final_kernel<<<NB, 32>>>(out);                                      // 16 warps
}

// round 11
// speedup vs baseline: 1.1084x; 1.1084x over previous
#include <cuda_runtime.h>
#include <stdint.h>
#include <math.h>

// ---------------------------------------------------------------------------
// Problem constants
// ---------------------------------------------------------------------------
#define NB      16       // batch
#define NCLS    80       // classes
#define NANCH   25200    // 80*80*3 + 40*40*3 + 20*20*3
#define TOPK    128      // NMS_TOPK
#define MAXOUT  100
#define SCORE_THR 0.25f
#define IOU_THR   0.45f

#define K1_CELLS   16    // cells per block (divides 6400, 1600, 400, and 8400)
#define K1_THREADS 128
#define CAND_MAX   2048
#define CAP        16384 // per-(b,class) candidate capacity (mean ~9.1k, sigma ~80)

// ---------------------------------------------------------------------------
// Scratch (static __device__ arrays — no allocation allowed)
// ---------------------------------------------------------------------------
__device__ unsigned long long g_cand[(size_t)NB * NCLS * CAP];  // 168 MB candidate keys
__device__ unsigned g_ccnt[NB * NCLS];                          // per-task candidate counts
__device__ float g_boxes[(size_t)NB * NANCH * 4];               // (B, N, 4)
__device__ float g_cls_scores[NB * NCLS * MAXOUT];              // per-class NMS scores (-1 = invalid)
__device__ float g_cls_boxes[NB * NCLS * MAXOUT * 4];           // per-class NMS boxes

__constant__ float c_anchor_w[9] = {10.f, 16.f, 33.f, 30.f, 62.f, 59.f, 116.f, 156.f, 373.f};
__constant__ float c_anchor_h[9] = {13.f, 30.f, 23.f, 61.f, 45.f, 119.f, 90.f, 198.f, 326.f};

__device__ __forceinline__ float sigm(float x) {
    return 1.0f / (1.0f + expf(-x));
}

// ---------------------------------------------------------------------------
// K0: reset per-task candidate counters (graph replay safety)
// ---------------------------------------------------------------------------
__global__ void reset_kernel()
{
    int i = blockIdx.x * 256 + threadIdx.x;
    if (i < NB * NCLS) g_ccnt[i] = 0;
}

// ---------------------------------------------------------------------------
// K1: decode + candidate extraction (no dense score matrix).
// Block = 128 threads handles 16 cells (48 anchors, 4080 input floats).
// Class iteration is rotated per block to decorrelate atomic counter traffic.
// ---------------------------------------------------------------------------
__global__ __launch_bounds__(K1_THREADS) void decode_kernel(
    const float* __restrict__ p3, const float* __restrict__ p4, const float* __restrict__ p5)
{
    __shared__ float s_in[K1_CELLS * 255];     // 16320 B, contiguous input slab
    __shared__ float s_obj[K1_CELLS * 3];

    const int tid = threadIdx.x;
    const int lane = tid & 31;
    int cell0 = blockIdx.x * K1_CELLS;         // global cell index (B x 8400 cells)
    int b  = cell0 / 8400;
    int r0 = cell0 - b * 8400;                 // image-local cell

    const float* src; int W; float strd; int abase; int n0; int hw0;
    if (r0 < 6400)      { hw0 = r0;        W = 80; strd = 8.f;  abase = 0; src = p3 + ((size_t)b * 6400 + hw0) * 255; n0 = hw0 * 3; }
    else if (r0 < 8000) { hw0 = r0 - 6400; W = 40; strd = 16.f; abase = 3; src = p4 + ((size_t)b * 1600 + hw0) * 255; n0 = 19200 + hw0 * 3; }
    else                { hw0 = r0 - 8000; W = 20; strd = 32.f; abase = 6; src = p5 + ((size_t)b *  400 + hw0) * 255; n0 = 24000 + hw0 * 3; }

    // stage: fully coalesced contiguous copy
    #pragma unroll 4
    for (int i = tid; i < K1_CELLS * 255; i += K1_THREADS) s_in[i] = src[i];
    __syncthreads();

    // decode 48 anchors (threads 0..47); anchor j -> shared offset 85*j
    if (tid < K1_CELLS * 3) {
        int cl = tid / 3;
        int a  = tid - cl * 3;
        int hw = hw0 + cl;
        int y  = hw / W;
        int x  = hw - y * W;
        const float* q = s_in + tid * 85;      // cl*255 + a*85 == 85*tid

        float cx = (sigm(q[0]) + (float)x) * strd;
        float cy = (sigm(q[1]) + (float)y) * strd;
        float w  = expf(q[2]) * c_anchor_w[abase + a];
        float h  = expf(q[3]) * c_anchor_h[abase + a];

        float* bo = g_boxes + ((size_t)b * NANCH + n0 + tid) * 4;
        bo[0] = cx - w * 0.5f;
        bo[1] = cy - h * 0.5f;
        bo[2] = cx + w * 0.5f;
        bo[3] = cy + h * 0.5f;

        s_obj[tid] = sigm(q[4]);
    }
    __syncthreads();

    // scores: 48 anchors x 80 classes; warp-aggregated candidate append per class.
    // Class index rotated by blockIdx so concurrent blocks hit different counters.
    const int NA = K1_CELLS * 3;               // 48
    const int rot = blockIdx.x % NCLS;
    #pragma unroll 3
    for (int w = 0; w < (NA * NCLS) / K1_THREADS; ++w) {   // 30 iterations
        int idx = w * K1_THREADS + tid;
        int c = idx / NA;                      // warp spans at most 2 class groups
        int j = idx - c * NA;
        int cr = c + rot; if (cr >= NCLS) cr -= NCLS;      // rotated class (bijection)
        float v = s_obj[j] * sigm(s_in[j * 85 + 5 + cr]);  // 85-word stride: conflict-free
        bool pass = v > SCORE_THR;

        unsigned same    = __match_any_sync(0xFFFFFFFFu, cr);
        unsigned actSame = __ballot_sync(0xFFFFFFFFu, pass) & same;
        int leader = __ffs(actSame) - 1;
        unsigned base = 0;
        if (pass && lane == leader)
            base = atomicAdd(&g_ccnt[b * NCLS + cr], __popc(actSame));
        base = __shfl_sync(0xFFFFFFFFu, base, leader >= 0 ? leader : 0);
        if (pass) {
            unsigned p = base + __popc(actSame & ((1u << lane) - 1u));
            if (p < CAP) {
                int n = n0 + j;
                g_cand[((size_t)(b * NCLS + cr)) * CAP + p] =
                    ((unsigned long long)__float_as_uint(v) << 32) | (unsigned)(0x00FFFFFF - n);
            }
        }
    }
}

// ---------------------------------------------------------------------------
// K2: per (b, class): exact top-128 via histogram threshold over the compact
// candidate list + small sort + NMS. one block of 256 threads per task.
// ---------------------------------------------------------------------------
__global__ __launch_bounds__(256) void topk_nms_kernel()
{
    const int task = blockIdx.x;
    const int b = task / NCLS;
    const int tid = threadIdx.x;

    const unsigned long long* __restrict__ cand = g_cand + (size_t)task * CAP;
    const int cnt = (int)min(g_ccnt[task], (unsigned)CAP);

    __shared__ unsigned long long s_cand[CAND_MAX];        // 16 KB; aliased as hist in pass A
    unsigned* hist = (unsigned*)s_cand;                    // 4096 buckets
    __shared__ unsigned s_csum[256];
    __shared__ unsigned s_T, s_cnt;

    // --- pass A: histogram of score bits (scores in (0.25, 1) span exactly 2^24 codes) ---
    for (int i = tid; i < 4096; i += 256) hist[i] = 0;
    __syncthreads();

    for (int i = tid; i < cnt; i += 256) {
        unsigned ub = (unsigned)(cand[i] >> 32);
        unsigned bk = min((ub - 0x3E800000u) >> 12, 4095u);
        atomicAdd(&hist[bk], 1u);
    }
    __syncthreads();

    // --- per-thread chunk sums (16 buckets each) ---
    unsigned sum = 0;
    #pragma unroll
    for (int k = 0; k < 16; ++k) sum += hist[tid * 16 + k];
    s_csum[tid] = sum;
    __syncthreads();

    // --- thread 0: find threshold bucket T (suffix count first >= 128) ---
    if (tid == 0) {
        unsigned acc = 0;
        int ch;
        for (ch = 255; ch >= 0; --ch) {
            if (acc + s_csum[ch] >= TOPK) break;
            acc += s_csum[ch];
        }
        unsigned T = 0;
        if (ch >= 0) {
            for (int q = ch * 16 + 15; q >= ch * 16; --q) {
                acc += hist[q];
                if (acc >= TOPK) { T = (unsigned)q; break; }
            }
        }
        s_T = T;
        s_cnt = 0;
    }
    __syncthreads();

    // --- pass B: collect candidate keys with bucket >= T (overwrites hist region) ---
    unsigned T = s_T;
    for (int i = tid; i < cnt; i += 256) {
        unsigned long long key = cand[i];
        unsigned ub = (unsigned)(key >> 32);
        unsigned bk = min((ub - 0x3E800000u) >> 12, 4095u);
        if (bk >= T) {
            unsigned p = atomicAdd(&s_cnt, 1u);
            if (p < CAND_MAX) s_cand[p] = key;
        }
    }
    __syncthreads();

    int ccnt = (int)min(s_cnt, (unsigned)CAND_MAX);
    int P = TOPK;
    while (P < ccnt) P <<= 1;                  // power-of-two sort size >= max(ccnt, 128)
    for (int i = ccnt + tid; i < P; i += 256) s_cand[i] = 0ull;
    __syncthreads();

    // --- bitonic sort P keys descending (P typically 128 or 256) ---
    for (int k = 2; k <= P; k <<= 1) {
        for (int j = k >> 1; j > 0; j >>= 1) {
            for (int i = tid; i < P; i += 256) {
                int l = i ^ j;
                if (l > i) {
                    unsigned long long a  = s_cand[i];
                    unsigned long long bb = s_cand[l];
                    bool desc = ((i & k) == 0);
                    if ((a < bb) == desc) { s_cand[i] = bb; s_cand[l] = a; }
                }
            }
            __syncthreads();
        }
    }

    // --- gather top-128 candidates ---
    __shared__ float s_bx1[TOPK], s_by1[TOPK], s_bx2[TOPK], s_by2[TOPK];
    __shared__ float s_area[TOPK], s_score[TOPK];
    __shared__ unsigned s_sup[TOPK][4];
    __shared__ unsigned s_keep[4];
    __shared__ unsigned s_vball[4];

    if (tid < MAXOUT) g_cls_scores[task * MAXOUT + tid] = -1.0f;   // default invalid

    if (tid < TOPK) {
        unsigned long long key = s_cand[tid];
        float s = __uint_as_float((unsigned)(key >> 32));
        int n = 0x00FFFFFF - (int)(unsigned)(key & 0xFFFFFFFFull);
        if (!(s > 0.f)) n = 0;     // padding slot: any in-range box, never used
        s_score[tid] = s;
        const float* bp = g_boxes + ((size_t)b * NANCH + n) * 4;
        float x1 = bp[0], y1 = bp[1], x2 = bp[2], y2 = bp[3];
        s_bx1[tid] = x1; s_by1[tid] = y1; s_bx2[tid] = x2; s_by2[tid] = y2;
        s_area[tid] = (x2 - x1) * (y2 - y1);
    }
    __syncthreads();

    // --- suppression bitmask: s_sup[i][w] bit t set iff j=32w+t > i and iou(i,j) > thr ---
    for (int wi = tid; wi < TOPK * 4; wi += 256) {
        int i = wi >> 2;
        int w = wi & 3;
        float ax1 = s_bx1[i], ay1 = s_by1[i], ax2 = s_bx2[i], ay2 = s_by2[i], aa = s_area[i];
        unsigned m = 0;
        #pragma unroll 4
        for (int tt = 0; tt < 32; ++tt) {
            int j = (w << 5) + tt;
            if (j > i) {
                float iw = fmaxf(fminf(ax2, s_bx2[j]) - fmaxf(ax1, s_bx1[j]), 0.f);
                float ih = fmaxf(fminf(ay2, s_by2[j]) - fmaxf(ay1, s_by1[j]), 0.f);
                float inter = iw * ih;
                float iou = inter / (aa + s_area[j] - inter + 1e-9f);
                if (iou > IOU_THR) m |= (1u << tt);
            }
        }
        s_sup[i][w] = m;
    }
    __syncthreads();

    // --- sequential NMS scan (the lax.scan) on 128-bit bitmask ---
    if (tid == 0) {
        unsigned k0 = 0xFFFFFFFFu, k1 = 0xFFFFFFFFu, k2 = 0xFFFFFFFFu, k3 = 0xFFFFFFFFu;
        for (int i = 0; i < TOPK; ++i) {
            unsigned kw = (i < 32) ? k0 : (i < 64) ? k1 : (i < 96) ? k2 : k3;
            if (((kw >> (i & 31)) & 1u) && (s_score[i] > 0.f)) {
                k0 &= ~s_sup[i][0]; k1 &= ~s_sup[i][1]; k2 &= ~s_sup[i][2]; k3 &= ~s_sup[i][3];
            }
        }
        s_keep[0] = k0; s_keep[1] = k1; s_keep[2] = k2; s_keep[3] = k3;
    }
    __syncthreads();

    // --- compact valid survivors in order -> per-class top-100 ---
    bool valid = false;
    if (tid < TOPK) {
        valid = (((s_keep[tid >> 5] >> (tid & 31)) & 1u) != 0) && (s_score[tid] > 0.f);
        unsigned bal = __ballot_sync(0xFFFFFFFFu, valid);
        if ((tid & 31) == 0) s_vball[tid >> 5] = bal;
    }
    __syncthreads();

    if (tid < TOPK && valid) {
        int w = tid >> 5;
        int pos = __popc(s_vball[w] & ((1u << (tid & 31)) - 1u));
        #pragma unroll
        for (int q = 0; q < 4; ++q) if (q < w) pos += __popc(s_vball[q]);
        if (pos < MAXOUT) {
            size_t o = (size_t)task * MAXOUT + pos;
            g_cls_scores[o] = s_score[tid];
            float* ob = g_cls_boxes + o * 4;
            ob[0] = s_bx1[tid]; ob[1] = s_by1[tid]; ob[2] = s_bx2[tid]; ob[3] = s_by2[tid];
        }
    }
}

// ---------------------------------------------------------------------------
// K3: per-image top-100 over the 8000 per-class slots via histogram threshold
// (parallel two-pass selection; no dependent-load chain). 256 threads/image.
// ---------------------------------------------------------------------------
#define F_CAND 1024
__global__ __launch_bounds__(256) void final_kernel(float* __restrict__ out)
{
    const int b = blockIdx.x;
    const int tid = threadIdx.x;
    const float* __restrict__ scores = g_cls_scores + b * NCLS * MAXOUT;

    __shared__ unsigned hist[4096];            // 16 KB
    __shared__ unsigned long long s_cand[F_CAND];
    __shared__ unsigned s_csum[256];
    __shared__ unsigned s_T, s_cnt, s_total;

    for (int i = tid; i < 4096; i += 256) hist[i] = 0;
    __syncthreads();

    // pass A: histogram over valid scores (valid > SCORE_THR; invalid = -1)
    for (int i = tid; i < NCLS * MAXOUT; i += 256) {
        float s = scores[i];
        if (s > 0.f) {
            unsigned bk = min((__float_as_uint(s) - 0x3E800000u) >> 12, 4095u);
            atomicAdd(&hist[bk], 1u);
        }
    }
    __syncthreads();

    unsigned sum = 0;
    #pragma unroll
    for (int k = 0; k < 16; ++k) sum += hist[tid * 16 + k];
    s_csum[tid] = sum;
    __syncthreads();

    if (tid == 0) {
        unsigned total = 0;
        for (int q = 0; q < 256; ++q) total += s_csum[q];
        unsigned acc = 0;
        int ch;
        for (ch = 255; ch >= 0; --ch) {
            if (acc + s_csum[ch] >= MAXOUT) break;
            acc += s_csum[ch];
        }
        unsigned T = 0;
        if (ch >= 0) {
            for (int q = ch * 16 + 15; q >= ch * 16; --q) {
                acc += hist[q];
                if (acc >= MAXOUT) { T = (unsigned)q; break; }
            }
        }
        s_T = T;
        s_cnt = 0;
        s_total = total;
    }
    __syncthreads();

    // pass B: collect keys (score bits desc, flat index asc via inversion)
    unsigned T = s_T;
    for (int i = tid; i < NCLS * MAXOUT; i += 256) {
        float s = scores[i];
        if (s > 0.f) {
            unsigned ub = __float_as_uint(s);
            unsigned bk = min((ub - 0x3E800000u) >> 12, 4095u);
            if (bk >= T) {
                unsigned p = atomicAdd(&s_cnt, 1u);
                if (p < F_CAND)
                    s_cand[p] = ((unsigned long long)ub << 32) | (unsigned)(0x1FFFu - i);
            }
        }
    }
    __syncthreads();

    int ccnt = (int)min(s_cnt, (unsigned)F_CAND);
    int P = 128;                               // >= MAXOUT, power of two
    while (P < ccnt) P <<= 1;
    for (int i = ccnt + tid; i < P; i += 256) s_cand[i] = 0ull;
    __syncthreads();

    // bitonic sort P keys descending
    for (int k = 2; k <= P; k <<= 1) {
        for (int j = k >> 1; j > 0; j >>= 1) {
            for (int i = tid; i < P; i += 256) {
                int l = i ^ j;
                if (l > i) {
                    unsigned long long a  = s_cand[i];
                    unsigned long long bb = s_cand[l];
                    bool desc = ((i & k) == 0);
                    if ((a < bb) == desc) { s_cand[i] = bb; s_cand[l] = a; }
                }
            }
            __syncthreads();
        }
    }

    // emit top-100 (parallel gather of boxes)
    if (tid < MAXOUT) {
        unsigned long long key = s_cand[tid];
        bool val = key != 0ull;
        float* ob = out + ((size_t)b * MAXOUT + tid) * 4;
        if (val) {
            int flat = 0x1FFF - (int)(unsigned)(key & 0xFFFFFFFFull);
            float s = __uint_as_float((unsigned)(key >> 32));
            const float* bp = g_cls_boxes + ((size_t)b * NCLS * MAXOUT + flat) * 4;
            ob[0] = bp[0]; ob[1] = bp[1]; ob[2] = bp[2]; ob[3] = bp[3];
            out[NB * MAXOUT * 4 + b * MAXOUT + tid] = s;
            out[NB * MAXOUT * 5 + b * MAXOUT + tid] = (float)(flat / MAXOUT);
        } else {
            ob[0] = 0.f; ob[1] = 0.f; ob[2] = 0.f; ob[3] = 0.f;
            out[NB * MAXOUT * 4 + b * MAXOUT + tid] = 0.f;
            out[NB * MAXOUT * 5 + b * MAXOUT + tid] = 0.f;
        }
    }
    if (tid == 0)
        out[NB * MAXOUT * 6 + b] = (float)min(s_total, (unsigned)MAXOUT);
}

// ---------------------------------------------------------------------------
// Entry point
// ---------------------------------------------------------------------------
extern "C" void kernel_launch(void* const* d_in, const int* in_sizes, int n_in,
                              void* d_out, int out_size)
{
    // identify inputs by element count (robust to ordering)
    const float* p3 = nullptr; const float* p4 = nullptr; const float* p5 = nullptr;
    for (int i = 0; i < n_in; ++i) {
        if      (in_sizes[i] == 16 * 80 * 80 * 255) p3 = (const float*)d_in[i];
        else if (in_sizes[i] == 16 * 40 * 40 * 255) p4 = (const float*)d_in[i];
        else if (in_sizes[i] == 16 * 20 * 20 * 255) p5 = (const float*)d_in[i];
    }
    float* out = (float*)d_out;

    reset_kernel<<<(NB * NCLS + 255) / 256, 256>>>();
    decode_kernel<<<(NB * 8400) / K1_CELLS, K1_THREADS>>>(p3, p4, p5);  // 8400 blocks
    topk_nms_kernel<<<NB * NCLS, 256>>>();                              // 1280 blocks
    final_kernel<<<NB, 256>>>(out);                                     // 16 blocks
}

// round 12
// speedup vs baseline: 1.1278x; 1.0175x over previous
#include <cuda_runtime.h>
#include <stdint.h>
#include <math.h>

// ---------------------------------------------------------------------------
// Problem constants
// ---------------------------------------------------------------------------
#define NB      16       // batch
#define NCLS    80       // classes
#define NANCH   25200    // 80*80*3 + 40*40*3 + 20*20*3
#define TOPK    128      // NMS_TOPK
#define MAXOUT  100
#define SCORE_THR 0.25f
#define IOU_THR   0.45f

#define K1_CELLS   16    // cells per block (divides 6400, 1600, 400, and 8400)
#define K1_THREADS 128
#define CAND_MAX   2048

// ---------------------------------------------------------------------------
// Scratch (static __device__ arrays — no allocation allowed)
// ---------------------------------------------------------------------------
__device__ float g_scores[(size_t)NB * NCLS * NANCH];      // (B, C, N) class-major, 129 MB
__device__ float g_boxes[(size_t)NB * NANCH * 4];          // (B, N, 4)
__device__ float g_cls_scores[NB * NCLS * MAXOUT];         // per-class NMS scores (-1 = invalid)
__device__ float g_cls_boxes[NB * NCLS * MAXOUT * 4];      // per-class NMS boxes

__constant__ float c_anchor_w[9] = {10.f, 16.f, 33.f, 30.f, 62.f, 59.f, 116.f, 156.f, 373.f};
__constant__ float c_anchor_h[9] = {13.f, 30.f, 23.f, 61.f, 45.f, 119.f, 90.f, 198.f, 326.f};

__device__ __forceinline__ float sigm(float x) {
    return 1.0f / (1.0f + expf(-x));
}

// ---------------------------------------------------------------------------
// K1: decode + score transpose, shared-staged for coalesced loads.
// (round-4 structure, measured 69.7us)
// ---------------------------------------------------------------------------
__global__ __launch_bounds__(K1_THREADS) void decode_kernel(
    const float* __restrict__ p3, const float* __restrict__ p4, const float* __restrict__ p5)
{
    __shared__ float s_in[K1_CELLS * 255];     // 16320 B, contiguous input slab
    __shared__ float s_obj[K1_CELLS * 3];

    const int tid = threadIdx.x;
    int cell0 = blockIdx.x * K1_CELLS;         // global cell index (B x 8400 cells)
    int b  = cell0 / 8400;
    int r0 = cell0 - b * 8400;                 // image-local cell

    const float* src; int W; float strd; int abase; int n0; int hw0;
    if (r0 < 6400)      { hw0 = r0;        W = 80; strd = 8.f;  abase = 0; src = p3 + ((size_t)b * 6400 + hw0) * 255; n0 = hw0 * 3; }
    else if (r0 < 8000) { hw0 = r0 - 6400; W = 40; strd = 16.f; abase = 3; src = p4 + ((size_t)b * 1600 + hw0) * 255; n0 = 19200 + hw0 * 3; }
    else                { hw0 = r0 - 8000; W = 20; strd = 32.f; abase = 6; src = p5 + ((size_t)b *  400 + hw0) * 255; n0 = 24000 + hw0 * 3; }

    // stage: fully coalesced contiguous copy
    #pragma unroll 4
    for (int i = tid; i < K1_CELLS * 255; i += K1_THREADS) s_in[i] = src[i];
    __syncthreads();

    // decode 48 anchors (threads 0..47); anchor j -> shared offset 85*j
    if (tid < K1_CELLS * 3) {
        int cl = tid / 3;
        int a  = tid - cl * 3;
        int hw = hw0 + cl;
        int y  = hw / W;
        int x  = hw - y * W;
        const float* q = s_in + tid * 85;      // cl*255 + a*85 == 85*tid

        float cx = (sigm(q[0]) + (float)x) * strd;
        float cy = (sigm(q[1]) + (float)y) * strd;
        float w  = expf(q[2]) * c_anchor_w[abase + a];
        float h  = expf(q[3]) * c_anchor_h[abase + a];

        float* bo = g_boxes + ((size_t)b * NANCH + n0 + tid) * 4;
        bo[0] = cx - w * 0.5f;
        bo[1] = cy - h * 0.5f;
        bo[2] = cx + w * 0.5f;
        bo[3] = cy + h * 0.5f;

        s_obj[tid] = sigm(q[4]);
    }
    __syncthreads();

    // scores: 48 anchors x 80 classes = 3840 ops; stores coalesced in 48-float runs
    const int NA = K1_CELLS * 3;               // 48
    #pragma unroll 5
    for (int w = 0; w < (NA * NCLS) / K1_THREADS; ++w) {   // 30 iterations
        int idx = w * K1_THREADS + tid;
        int c = idx / NA;
        int j = idx - c * NA;
        float v = s_obj[j] * sigm(s_in[j * 85 + 5 + c]);   // 85-word stride: conflict-free
        g_scores[((size_t)b * NCLS + c) * NANCH + n0 + j] = v;
    }
}

// ---------------------------------------------------------------------------
// K2: per (b, class): exact top-128 via histogram threshold + small sort + NMS.
// Warp-aggregated histogram atomics (scores cluster in low buckets).
// one block of 256 threads per task; 1280 blocks
// ---------------------------------------------------------------------------
#define NANCH_PAD ((NANCH + 255) & ~255)       // 25344: full-warp loop bound

__global__ __launch_bounds__(256) void topk_nms_kernel()
{
    const int task = blockIdx.x;
    const int b = task / NCLS;
    const int c = task - b * NCLS;
    const int tid = threadIdx.x;
    const int lane = tid & 31;

    const float* __restrict__ srow = g_scores + ((size_t)b * NCLS + c) * NANCH;

    __shared__ unsigned long long s_cand[CAND_MAX];        // 16 KB; aliased as hist in pass A
    unsigned* hist = (unsigned*)s_cand;                    // 4096 buckets
    __shared__ unsigned s_csum[256];
    __shared__ unsigned s_T, s_cnt;

    // --- pass A: histogram of score bits (scores in (0.25, 1) span exactly 2^24 codes) ---
    for (int i = tid; i < 4096; i += 256) hist[i] = 0;
    __syncthreads();

    for (int n = tid; n < NANCH_PAD; n += 256) {           // full warps every iteration
        float s = (n < NANCH) ? srow[n] : 0.f;
        bool pass = s > SCORE_THR;
        unsigned active = __ballot_sync(0xFFFFFFFFu, pass);
        if (pass) {
            unsigned bk = min((__float_as_uint(s) - 0x3E800000u) >> 12, 4095u);
            unsigned same = __match_any_sync(active, bk);   // pass-lanes with equal bucket
            int leader = __ffs(same) - 1;
            if (lane == leader) atomicAdd(&hist[bk], __popc(same));
        }
    }
    __syncthreads();

    // --- per-thread chunk sums (16 buckets each) ---
    unsigned sum = 0;
    #pragma unroll
    for (int k = 0; k < 16; ++k) sum += hist[tid * 16 + k];
    s_csum[tid] = sum;
    __syncthreads();

    // --- thread 0: find threshold bucket T (suffix count first >= 128) ---
    if (tid == 0) {
        unsigned acc = 0;
        int ch;
        for (ch = 255; ch >= 0; --ch) {
            if (acc + s_csum[ch] >= TOPK) break;
            acc += s_csum[ch];
        }
        unsigned T = 0;
        if (ch >= 0) {
            for (int q = ch * 16 + 15; q >= ch * 16; --q) {
                acc += hist[q];
                if (acc >= TOPK) { T = (unsigned)q; break; }
            }
        }
        s_T = T;
        s_cnt = 0;
    }
    __syncthreads();

    // --- pass B: collect keys with bucket >= T (warp-aggregated append) ---
    unsigned T = s_T;
    for (int n = tid; n < NANCH_PAD; n += 256) {
        float s = (n < NANCH) ? srow[n] : 0.f;
        unsigned ub = __float_as_uint(s);
        bool keep = (s > SCORE_THR) && (min((ub - 0x3E800000u) >> 12, 4095u) >= T);
        unsigned grp = __ballot_sync(0xFFFFFFFFu, keep);
        if (keep) {
            int leader = __ffs(grp) - 1;
            unsigned base = 0;
            if (lane == leader) base = atomicAdd(&s_cnt, __popc(grp));
            base = __shfl_sync(grp, base, leader);
            unsigned p = base + __popc(grp & ((1u << lane) - 1u));
            if (p < CAND_MAX)
                s_cand[p] = ((unsigned long long)ub << 32) | (unsigned)(0x00FFFFFF - n);
        }
    }
    __syncthreads();

    int ccnt = (int)min(s_cnt, (unsigned)CAND_MAX);
    int P = TOPK;
    while (P < ccnt) P <<= 1;                  // power-of-two sort size >= max(ccnt, 128)
    for (int i = ccnt + tid; i < P; i += 256) s_cand[i] = 0ull;
    __syncthreads();

    // --- bitonic sort P keys descending (P typically 128 or 256) ---
    for (int k = 2; k <= P; k <<= 1) {
        for (int j = k >> 1; j > 0; j >>= 1) {
            for (int i = tid; i < P; i += 256) {
                int l = i ^ j;
                if (l > i) {
                    unsigned long long a  = s_cand[i];
                    unsigned long long bb = s_cand[l];
                    bool desc = ((i & k) == 0);
                    if ((a < bb) == desc) { s_cand[i] = bb; s_cand[l] = a; }
                }
            }
            __syncthreads();
        }
    }

    // --- gather top-128 candidates ---
    __shared__ float s_bx1[TOPK], s_by1[TOPK], s_bx2[TOPK], s_by2[TOPK];
    __shared__ float s_area[TOPK], s_score[TOPK];
    __shared__ unsigned s_sup[TOPK][4];
    __shared__ unsigned s_keep[4];
    __shared__ unsigned s_vball[4];

    if (tid < MAXOUT) g_cls_scores[task * MAXOUT + tid] = -1.0f;   // default invalid

    if (tid < TOPK) {
        unsigned long long key = s_cand[tid];
        float s = __uint_as_float((unsigned)(key >> 32));
        int n = 0x00FFFFFF - (int)(unsigned)(key & 0xFFFFFFFFull);
        if (!(s > 0.f)) n = 0;     // padding slot: any in-range box, never used
        s_score[tid] = s;
        const float* bp = g_boxes + ((size_t)b * NANCH + n) * 4;
        float x1 = bp[0], y1 = bp[1], x2 = bp[2], y2 = bp[3];
        s_bx1[tid] = x1; s_by1[tid] = y1; s_bx2[tid] = x2; s_by2[tid] = y2;
        s_area[tid] = (x2 - x1) * (y2 - y1);
    }
    __syncthreads();

    // --- suppression bitmask: s_sup[i][w] bit t set iff j=32w+t > i and iou(i,j) > thr ---
    for (int wi = tid; wi < TOPK * 4; wi += 256) {
        int i = wi >> 2;
        int w = wi & 3;
        float ax1 = s_bx1[i], ay1 = s_by1[i], ax2 = s_bx2[i], ay2 = s_by2[i], aa = s_area[i];
        unsigned m = 0;
        #pragma unroll 4
        for (int tt = 0; tt < 32; ++tt) {
            int j = (w << 5) + tt;
            if (j > i) {
                float iw = fmaxf(fminf(ax2, s_bx2[j]) - fmaxf(ax1, s_bx1[j]), 0.f);
                float ih = fmaxf(fminf(ay2, s_by2[j]) - fmaxf(ay1, s_by1[j]), 0.f);
                float inter = iw * ih;
                float iou = inter / (aa + s_area[j] - inter + 1e-9f);
                if (iou > IOU_THR) m |= (1u << tt);
            }
        }
        s_sup[i][w] = m;
    }
    __syncthreads();

    // --- sequential NMS scan (the lax.scan) on 128-bit bitmask ---
    if (tid == 0) {
        unsigned k0 = 0xFFFFFFFFu, k1 = 0xFFFFFFFFu, k2 = 0xFFFFFFFFu, k3 = 0xFFFFFFFFu;
        for (int i = 0; i < TOPK; ++i) {
            unsigned kw = (i < 32) ? k0 : (i < 64) ? k1 : (i < 96) ? k2 : k3;
            if (((kw >> (i & 31)) & 1u) && (s_score[i] > 0.f)) {
                k0 &= ~s_sup[i][0]; k1 &= ~s_sup[i][1]; k2 &= ~s_sup[i][2]; k3 &= ~s_sup[i][3];
            }
        }
        s_keep[0] = k0; s_keep[1] = k1; s_keep[2] = k2; s_keep[3] = k3;
    }
    __syncthreads();

    // --- compact valid survivors in order -> per-class top-100 ---
    bool valid = false;
    if (tid < TOPK) {
        valid = (((s_keep[tid >> 5] >> (tid & 31)) & 1u) != 0) && (s_score[tid] > 0.f);
        unsigned bal = __ballot_sync(0xFFFFFFFFu, valid);
        if ((tid & 31) == 0) s_vball[tid >> 5] = bal;
    }
    __syncthreads();

    if (tid < TOPK && valid) {
        int w = tid >> 5;
        int pos = __popc(s_vball[w] & ((1u << (tid & 31)) - 1u));
        #pragma unroll
        for (int q = 0; q < 4; ++q) if (q < w) pos += __popc(s_vball[q]);
        if (pos < MAXOUT) {
            size_t o = (size_t)task * MAXOUT + pos;
            g_cls_scores[o] = s_score[tid];
            float* ob = g_cls_boxes + o * 4;
            ob[0] = s_bx1[tid]; ob[1] = s_by1[tid]; ob[2] = s_bx2[tid]; ob[3] = s_by2[tid];
        }
    }
}

// ---------------------------------------------------------------------------
// K3: per-image top-100 over the 8000 per-class slots via histogram threshold
// (parallel two-pass selection). 256 threads/image. (round-11, measured 16.6us)
// ---------------------------------------------------------------------------
#define F_CAND 1024
__global__ __launch_bounds__(256) void final_kernel(float* __restrict__ out)
{
    const int b = blockIdx.x;
    const int tid = threadIdx.x;
    const float* __restrict__ scores = g_cls_scores + b * NCLS * MAXOUT;

    __shared__ unsigned hist[4096];            // 16 KB
    __shared__ unsigned long long s_cand[F_CAND];
    __shared__ unsigned s_csum[256];
    __shared__ unsigned s_T, s_cnt, s_total;

    for (int i = tid; i < 4096; i += 256) hist[i] = 0;
    __syncthreads();

    // pass A: histogram over valid scores (valid > SCORE_THR; invalid = -1)
    for (int i = tid; i < NCLS * MAXOUT; i += 256) {
        float s = scores[i];
        if (s > 0.f) {
            unsigned bk = min((__float_as_uint(s) - 0x3E800000u) >> 12, 4095u);
            atomicAdd(&hist[bk], 1u);
        }
    }
    __syncthreads();

    unsigned sum = 0;
    #pragma unroll
    for (int k = 0; k < 16; ++k) sum += hist[tid * 16 + k];
    s_csum[tid] = sum;
    __syncthreads();

    if (tid == 0) {
        unsigned total = 0;
        for (int q = 0; q < 256; ++q) total += s_csum[q];
        unsigned acc = 0;
        int ch;
        for (ch = 255; ch >= 0; --ch) {
            if (acc + s_csum[ch] >= MAXOUT) break;
            acc += s_csum[ch];
        }
        unsigned T = 0;
        if (ch >= 0) {
            for (int q = ch * 16 + 15; q >= ch * 16; --q) {
                acc += hist[q];
                if (acc >= MAXOUT) { T = (unsigned)q; break; }
            }
        }
        s_T = T;
        s_cnt = 0;
        s_total = total;
    }
    __syncthreads();

    // pass B: collect keys (score bits desc, flat index asc via inversion)
    unsigned T = s_T;
    for (int i = tid; i < NCLS * MAXOUT; i += 256) {
        float s = scores[i];
        if (s > 0.f) {
            unsigned ub = __float_as_uint(s);
            unsigned bk = min((ub - 0x3E800000u) >> 12, 4095u);
            if (bk >= T) {
                unsigned p = atomicAdd(&s_cnt, 1u);
                if (p < F_CAND)
                    s_cand[p] = ((unsigned long long)ub << 32) | (unsigned)(0x1FFFu - i);
            }
        }
    }
    __syncthreads();

    int ccnt = (int)min(s_cnt, (unsigned)F_CAND);
    int P = 128;                               // >= MAXOUT, power of two
    while (P < ccnt) P <<= 1;
    for (int i = ccnt + tid; i < P; i += 256) s_cand[i] = 0ull;
    __syncthreads();

    // bitonic sort P keys descending
    for (int k = 2; k <= P; k <<= 1) {
        for (int j = k >> 1; j > 0; j >>= 1) {
            for (int i = tid; i < P; i += 256) {
                int l = i ^ j;
                if (l > i) {
                    unsigned long long a  = s_cand[i];
                    unsigned long long bb = s_cand[l];
                    bool desc = ((i & k) == 0);
                    if ((a < bb) == desc) { s_cand[i] = bb; s_cand[l] = a; }
                }
            }
            __syncthreads();
        }
    }

    // emit top-100 (parallel gather of boxes)
    if (tid < MAXOUT) {
        unsigned long long key = s_cand[tid];
        bool val = key != 0ull;
        float* ob = out + ((size_t)b * MAXOUT + tid) * 4;
        if (val) {
            int flat = 0x1FFF - (int)(unsigned)(key & 0xFFFFFFFFull);
            float s = __uint_as_float((unsigned)(key >> 32));
            const float* bp = g_cls_boxes + ((size_t)b * NCLS * MAXOUT + flat) * 4;
            ob[0] = bp[0]; ob[1] = bp[1]; ob[2] = bp[2]; ob[3] = bp[3];
            out[NB * MAXOUT * 4 + b * MAXOUT + tid] = s;
            out[NB * MAXOUT * 5 + b * MAXOUT + tid] = (float)(flat / MAXOUT);
        } else {
            ob[0] = 0.f; ob[1] = 0.f; ob[2] = 0.f; ob[3] = 0.f;
            out[NB * MAXOUT * 4 + b * MAXOUT + tid] = 0.f;
            out[NB * MAXOUT * 5 + b * MAXOUT + tid] = 0.f;
        }
    }
    if (tid == 0)
        out[NB * MAXOUT * 6 + b] = (float)min(s_total, (unsigned)MAXOUT);
}

// ---------------------------------------------------------------------------
// Entry point
// ---------------------------------------------------------------------------
extern "C" void kernel_launch(void* const* d_in, const int* in_sizes, int n_in,
                              void* d_out, int out_size)
{
    // identify inputs by element count (robust to ordering)
    const float* p3 = nullptr; const float* p4 = nullptr; const float* p5 = nullptr;
    for (int i = 0; i < n_in; ++i) {
        if      (in_sizes[i] == 16 * 80 * 80 * 255) p3 = (const float*)d_in[i];
        else if (in_sizes[i] == 16 * 40 * 40 * 255) p4 = (const float*)d_in[i];
        else if (in_sizes[i] == 16 * 20 * 20 * 255) p5 = (const float*)d_in[i];
    }
    float* out = (float*)d_out;

    decode_kernel<<<(NB * 8400) / K1_CELLS, K1_THREADS>>>(p3, p4, p5);  // 8400 blocks
    topk_nms_kernel<<<NB * NCLS, 256>>>();                              // 1280 blocks
    final_kernel<<<NB, 256>>>(out);                                     // 16 blocks
}

// round 13
// speedup vs baseline: 1.6433x; 1.4571x over previous
#include <cuda_runtime.h>
#include <stdint.h>
#include <math.h>

// ---------------------------------------------------------------------------
// Problem constants
// ---------------------------------------------------------------------------
#define NB      16       // batch
#define NCLS    80       // classes
#define NANCH   25200    // 80*80*3 + 40*40*3 + 20*20*3
#define TOPK    128      // NMS_TOPK
#define MAXOUT  100
#define SCORE_THR 0.25f
#define IOU_THR   0.45f

#define K1_CELLS   16
#define K1_THREADS 128
#define CAND_MAX   2048
#define FINAL_MAX  512
#define BK_HALF    2048u  // bucket index of score 0.5

// ---------------------------------------------------------------------------
// Scratch (static __device__ arrays — no allocation allowed)
// ---------------------------------------------------------------------------
__device__ float g_scores[(size_t)NB * NCLS * NANCH];      // (B, C, N) class-major, 129 MB
__device__ float g_boxes[(size_t)NB * NANCH * 4];          // (B, N, 4)
__device__ float g_cls_scores[NB * NCLS * MAXOUT];         // per-class NMS scores (-1 = invalid)
__device__ float g_cls_boxes[NB * NCLS * MAXOUT * 4];      // per-class NMS boxes

__constant__ float c_anchor_w[9] = {10.f, 16.f, 33.f, 30.f, 62.f, 59.f, 116.f, 156.f, 373.f};
__constant__ float c_anchor_h[9] = {13.f, 30.f, 23.f, 61.f, 45.f, 119.f, 90.f, 198.f, 326.f};

__device__ __forceinline__ float sigm(float x) {
    return 1.0f / (1.0f + expf(-x));
}

// ---------------------------------------------------------------------------
// K1: decode + score transpose (round-4 structure, measured ~69us)
// ---------------------------------------------------------------------------
__global__ __launch_bounds__(K1_THREADS) void decode_kernel(
    const float* __restrict__ p3, const float* __restrict__ p4, const float* __restrict__ p5)
{
    __shared__ float s_in[K1_CELLS * 255];
    __shared__ float s_obj[K1_CELLS * 3];

    const int tid = threadIdx.x;
    int cell0 = blockIdx.x * K1_CELLS;
    int b  = cell0 / 8400;
    int r0 = cell0 - b * 8400;

    const float* src; int W; float strd; int abase; int n0; int hw0;
    if (r0 < 6400)      { hw0 = r0;        W = 80; strd = 8.f;  abase = 0; src = p3 + ((size_t)b * 6400 + hw0) * 255; n0 = hw0 * 3; }
    else if (r0 < 8000) { hw0 = r0 - 6400; W = 40; strd = 16.f; abase = 3; src = p4 + ((size_t)b * 1600 + hw0) * 255; n0 = 19200 + hw0 * 3; }
    else                { hw0 = r0 - 8000; W = 20; strd = 32.f; abase = 6; src = p5 + ((size_t)b *  400 + hw0) * 255; n0 = 24000 + hw0 * 3; }

    #pragma unroll 4
    for (int i = tid; i < K1_CELLS * 255; i += K1_THREADS) s_in[i] = src[i];
    __syncthreads();

    if (tid < K1_CELLS * 3) {
        int cl = tid / 3;
        int a  = tid - cl * 3;
        int hw = hw0 + cl;
        int y  = hw / W;
        int x  = hw - y * W;
        const float* q = s_in + tid * 85;

        float cx = (sigm(q[0]) + (float)x) * strd;
        float cy = (sigm(q[1]) + (float)y) * strd;
        float w  = expf(q[2]) * c_anchor_w[abase + a];
        float h  = expf(q[3]) * c_anchor_h[abase + a];

        float* bo = g_boxes + ((size_t)b * NANCH + n0 + tid) * 4;
        bo[0] = cx - w * 0.5f;
        bo[1] = cy - h * 0.5f;
        bo[2] = cx + w * 0.5f;
        bo[3] = cy + h * 0.5f;

        s_obj[tid] = sigm(q[4]);
    }
    __syncthreads();

    const int NA = K1_CELLS * 3;               // 48
    #pragma unroll 5
    for (int w = 0; w < (NA * NCLS) / K1_THREADS; ++w) {   // 30 iterations
        int idx = w * K1_THREADS + tid;
        int c = idx / NA;
        int j = idx - c * NA;
        float v = s_obj[j] * sigm(s_in[j * 85 + 5 + c]);
        g_scores[((size_t)b * NCLS + c) * NANCH + n0 + j] = v;
    }
}

// ---------------------------------------------------------------------------
// K2: per (b, class): exact top-128, optimistic SINGLE dense pass.
// Pass A: histogram of all scores > 0.25 AND append keys with score > 0.5.
// If threshold bucket T >= bucket(0.5) (typical: 128th score ~0.75) and no
// overflow, the top-128 is already in smem -> filter + sort. Else exact
// fallback pass B (re-read). Plain atomics throughout (measured fastest).
// ---------------------------------------------------------------------------
__global__ __launch_bounds__(256) void topk_nms_kernel()
{
    const int task = blockIdx.x;
    const int b = task / NCLS;
    const int c = task - b * NCLS;
    const int tid = threadIdx.x;

    const float* __restrict__ srow = g_scores + ((size_t)b * NCLS + c) * NANCH;

    __shared__ unsigned hist[4096];                        // 16 KB
    __shared__ unsigned long long s_cand[CAND_MAX];        // 16 KB raw buffer
    __shared__ unsigned long long s_fin[FINAL_MAX];        // 4 KB filtered keys
    __shared__ unsigned s_csum[256];
    __shared__ unsigned s_T, s_cnt, s_acc, s_fcnt;

    for (int i = tid; i < 4096; i += 256) hist[i] = 0;
    if (tid == 0) { s_cnt = 0; s_fcnt = 0; }
    __syncthreads();

    // --- pass A: histogram + optimistic append (score > 0.5) ---
    for (int n = tid; n < NANCH; n += 256) {
        float s = srow[n];
        if (s > SCORE_THR) {
            unsigned ub = __float_as_uint(s);
            unsigned bk = min((ub - 0x3E800000u) >> 12, 4095u);
            atomicAdd(&hist[bk], 1u);
            if (bk >= BK_HALF) {
                unsigned p = atomicAdd(&s_cnt, 1u);
                if (p < CAND_MAX)
                    s_cand[p] = ((unsigned long long)ub << 32) | (unsigned)(0x00FFFFFF - n);
            }
        }
    }
    __syncthreads();

    // --- per-thread chunk sums (16 buckets each) ---
    unsigned sum = 0;
    #pragma unroll
    for (int k = 0; k < 16; ++k) sum += hist[tid * 16 + k];
    s_csum[tid] = sum;
    __syncthreads();

    // --- thread 0: threshold bucket T (suffix count first >= 128), acc = count >= T ---
    if (tid == 0) {
        unsigned acc = 0;
        int ch;
        for (ch = 255; ch >= 0; --ch) {
            if (acc + s_csum[ch] >= TOPK) break;
            acc += s_csum[ch];
        }
        unsigned T = 0;
        if (ch >= 0) {
            for (int q = ch * 16 + 15; q >= ch * 16; --q) {
                acc += hist[q];
                if (acc >= TOPK) { T = (unsigned)q; break; }
            }
        }
        s_T = T;
        s_acc = acc;                           // exact count of keys with bucket >= T
    }
    __syncthreads();

    const unsigned T = s_T;
    const unsigned acc = s_acc;
    const bool fast = (T >= BK_HALF) && (s_cnt <= CAND_MAX) && (acc <= FINAL_MAX);

    if (fast) {
        // filter raw buffer (~1100 keys) down to bucket >= T (~128-200 keys)
        int rc = (int)s_cnt;
        for (int i = tid; i < rc; i += 256) {
            unsigned long long key = s_cand[i];
            unsigned bk = min(((unsigned)(key >> 32) - 0x3E800000u) >> 12, 4095u);
            if (bk >= T) {
                unsigned p = atomicAdd(&s_fcnt, 1u);
                s_fin[p] = key;                // p < acc <= FINAL_MAX guaranteed
            }
        }
    } else {
        // --- exact fallback pass B: re-read row, collect bucket >= T ---
        for (int n = tid; n < NANCH; n += 256) {
            float s = srow[n];
            if (s > SCORE_THR) {
                unsigned ub = __float_as_uint(s);
                unsigned bk = min((ub - 0x3E800000u) >> 12, 4095u);
                if (bk >= T) {
                    unsigned p = atomicAdd(&s_fcnt, 1u);
                    if (p < CAND_MAX)
                        s_cand[p] = ((unsigned long long)ub << 32) | (unsigned)(0x00FFFFFF - n);
                }
            }
        }
    }
    __syncthreads();

    unsigned long long* buf = fast ? s_fin : s_cand;
    int bufcap = fast ? FINAL_MAX : CAND_MAX;
    int ccnt = (int)min(s_fcnt, (unsigned)bufcap);
    int P = TOPK;
    while (P < ccnt) P <<= 1;                  // pow2 >= max(ccnt, 128); P <= bufcap? yes: ccnt<=bufcap, bufcap pow2
    for (int i = ccnt + tid; i < P; i += 256) buf[i] = 0ull;
    __syncthreads();

    // --- bitonic sort P keys descending (P typically 128 or 256) ---
    for (int k = 2; k <= P; k <<= 1) {
        for (int j = k >> 1; j > 0; j >>= 1) {
            for (int i = tid; i < P; i += 256) {
                int l = i ^ j;
                if (l > i) {
                    unsigned long long a  = buf[i];
                    unsigned long long bb = buf[l];
                    bool desc = ((i & k) == 0);
                    if ((a < bb) == desc) { buf[i] = bb; buf[l] = a; }
                }
            }
            __syncthreads();
        }
    }

    // --- gather top-128 candidates ---
    __shared__ float s_bx1[TOPK], s_by1[TOPK], s_bx2[TOPK], s_by2[TOPK];
    __shared__ float s_area[TOPK], s_score[TOPK];
    __shared__ unsigned s_sup[TOPK][4];
    __shared__ unsigned s_keep[4];
    __shared__ unsigned s_vball[4];

    if (tid < MAXOUT) g_cls_scores[task * MAXOUT + tid] = -1.0f;   // default invalid

    if (tid < TOPK) {
        unsigned long long key = buf[tid];
        float s = __uint_as_float((unsigned)(key >> 32));
        int n = 0x00FFFFFF - (int)(unsigned)(key & 0xFFFFFFFFull);
        if (!(s > 0.f)) n = 0;     // padding slot: any in-range box, never used
        s_score[tid] = s;
        const float* bp = g_boxes + ((size_t)b * NANCH + n) * 4;
        float x1 = bp[0], y1 = bp[1], x2 = bp[2], y2 = bp[3];
        s_bx1[tid] = x1; s_by1[tid] = y1; s_bx2[tid] = x2; s_by2[tid] = y2;
        s_area[tid] = (x2 - x1) * (y2 - y1);
    }
    __syncthreads();

    // --- suppression bitmask ---
    for (int wi = tid; wi < TOPK * 4; wi += 256) {
        int i = wi >> 2;
        int w = wi & 3;
        float ax1 = s_bx1[i], ay1 = s_by1[i], ax2 = s_bx2[i], ay2 = s_by2[i], aa = s_area[i];
        unsigned m = 0;
        #pragma unroll 4
        for (int tt = 0; tt < 32; ++tt) {
            int j = (w << 5) + tt;
            if (j > i) {
                float iw = fmaxf(fminf(ax2, s_bx2[j]) - fmaxf(ax1, s_bx1[j]), 0.f);
                float ih = fmaxf(fminf(ay2, s_by2[j]) - fmaxf(ay1, s_by1[j]), 0.f);
                float inter = iw * ih;
                float iou = inter / (aa + s_area[j] - inter + 1e-9f);
                if (iou > IOU_THR) m |= (1u << tt);
            }
        }
        s_sup[i][w] = m;
    }
    __syncthreads();

    // --- sequential NMS scan on 128-bit bitmask ---
    if (tid == 0) {
        unsigned k0 = 0xFFFFFFFFu, k1 = 0xFFFFFFFFu, k2 = 0xFFFFFFFFu, k3 = 0xFFFFFFFFu;
        for (int i = 0; i < TOPK; ++i) {
            unsigned kw = (i < 32) ? k0 : (i < 64) ? k1 : (i < 96) ? k2 : k3;
            if (((kw >> (i & 31)) & 1u) && (s_score[i] > 0.f)) {
                k0 &= ~s_sup[i][0]; k1 &= ~s_sup[i][1]; k2 &= ~s_sup[i][2]; k3 &= ~s_sup[i][3];
            }
        }
        s_keep[0] = k0; s_keep[1] = k1; s_keep[2] = k2; s_keep[3] = k3;
    }
    __syncthreads();

    // --- compact valid survivors in order -> per-class top-100 ---
    bool valid = false;
    if (tid < TOPK) {
        valid = (((s_keep[tid >> 5] >> (tid & 31)) & 1u) != 0) && (s_score[tid] > 0.f);
        unsigned bal = __ballot_sync(0xFFFFFFFFu, valid);
        if ((tid & 31) == 0) s_vball[tid >> 5] = bal;
    }
    __syncthreads();

    if (tid < TOPK && valid) {
        int w = tid >> 5;
        int pos = __popc(s_vball[w] & ((1u << (tid & 31)) - 1u));
        #pragma unroll
        for (int q = 0; q < 4; ++q) if (q < w) pos += __popc(s_vball[q]);
        if (pos < MAXOUT) {
            size_t o = (size_t)task * MAXOUT + pos;
            g_cls_scores[o] = s_score[tid];
            float* ob = g_cls_boxes + o * 4;
            ob[0] = s_bx1[tid]; ob[1] = s_by1[tid]; ob[2] = s_bx2[tid]; ob[3] = s_by2[tid];
        }
    }
}

// ---------------------------------------------------------------------------
// K3: per-image top-100 via histogram threshold (round-11, measured 16.6us)
// ---------------------------------------------------------------------------
#define F_CAND 1024
__global__ __launch_bounds__(256) void final_kernel(float* __restrict__ out)
{
    const int b = blockIdx.x;
    const int tid = threadIdx.x;
    const float* __restrict__ scores = g_cls_scores + b * NCLS * MAXOUT;

    __shared__ unsigned hist[4096];
    __shared__ unsigned long long s_cand[F_CAND];
    __shared__ unsigned s_csum[256];
    __shared__ unsigned s_T, s_cnt, s_total;

    for (int i = tid; i < 4096; i += 256) hist[i] = 0;
    __syncthreads();

    for (int i = tid; i < NCLS * MAXOUT; i += 256) {
        float s = scores[i];
        if (s > 0.f) {
            unsigned bk = min((__float_as_uint(s) - 0x3E800000u) >> 12, 4095u);
            atomicAdd(&hist[bk], 1u);
        }
    }
    __syncthreads();

    unsigned sum = 0;
    #pragma unroll
    for (int k = 0; k < 16; ++k) sum += hist[tid * 16 + k];
    s_csum[tid] = sum;
    __syncthreads();

    if (tid == 0) {
        unsigned total = 0;
        for (int q = 0; q < 256; ++q) total += s_csum[q];
        unsigned acc = 0;
        int ch;
        for (ch = 255; ch >= 0; --ch) {
            if (acc + s_csum[ch] >= MAXOUT) break;
            acc += s_csum[ch];
        }
        unsigned T = 0;
        if (ch >= 0) {
            for (int q = ch * 16 + 15; q >= ch * 16; --q) {
                acc += hist[q];
                if (acc >= MAXOUT) { T = (unsigned)q; break; }
            }
        }
        s_T = T;
        s_cnt = 0;
        s_total = total;
    }
    __syncthreads();

    unsigned T = s_T;
    for (int i = tid; i < NCLS * MAXOUT; i += 256) {
        float s = scores[i];
        if (s > 0.f) {
            unsigned ub = __float_as_uint(s);
            unsigned bk = min((ub - 0x3E800000u) >> 12, 4095u);
            if (bk >= T) {
                unsigned p = atomicAdd(&s_cnt, 1u);
                if (p < F_CAND)
                    s_cand[p] = ((unsigned long long)ub << 32) | (unsigned)(0x1FFFu - i);
            }
        }
    }
    __syncthreads();

    int ccnt = (int)min(s_cnt, (unsigned)F_CAND);
    int P = 128;
    while (P < ccnt) P <<= 1;
    for (int i = ccnt + tid; i < P; i += 256) s_cand[i] = 0ull;
    __syncthreads();

    for (int k = 2; k <= P; k <<= 1) {
        for (int j = k >> 1; j > 0; j >>= 1) {
            for (int i = tid; i < P; i += 256) {
                int l = i ^ j;
                if (l > i) {
                    unsigned long long a  = s_cand[i];
                    unsigned long long bb = s_cand[l];
                    bool desc = ((i & k) == 0);
                    if ((a < bb) == desc) { s_cand[i] = bb; s_cand[l] = a; }
                }
            }
            __syncthreads();
        }
    }

    if (tid < MAXOUT) {
        unsigned long long key = s_cand[tid];
        bool val = key != 0ull;
        float* ob = out + ((size_t)b * MAXOUT + tid) * 4;
        if (val) {
            int flat = 0x1FFF - (int)(unsigned)(key & 0xFFFFFFFFull);
            float s = __uint_as_float((unsigned)(key >> 32));
            const float* bp = g_cls_boxes + ((size_t)b * NCLS * MAXOUT + flat) * 4;
            ob[0] = bp[0]; ob[1] = bp[1]; ob[2] = bp[2]; ob[3] = bp[3];
            out[NB * MAXOUT * 4 + b * MAXOUT + tid] = s;
            out[NB * MAXOUT * 5 + b * MAXOUT + tid] = (float)(flat / MAXOUT);
        } else {
            ob[0] = 0.f; ob[1] = 0.f; ob[2] = 0.f; ob[3] = 0.f;
            out[NB * MAXOUT * 4 + b * MAXOUT + tid] = 0.f;
            out[NB * MAXOUT * 5 + b * MAXOUT + tid] = 0.f;
        }
    }
    if (tid == 0)
        out[NB * MAXOUT * 6 + b] = (float)min(s_total, (unsigned)MAXOUT);
}

// ---------------------------------------------------------------------------
// Entry point
// ---------------------------------------------------------------------------
extern "C" void kernel_launch(void* const* d_in, const int* in_sizes, int n_in,
                              void* d_out, int out_size)
{
    const float* p3 = nullptr; const float* p4 = nullptr; const float* p5 = nullptr;
    for (int i = 0; i < n_in; ++i) {
        if      (in_sizes[i] == 16 * 80 * 80 * 255) p3 = (const float*)d_in[i];
        else if (in_sizes[i] == 16 * 40 * 40 * 255) p4 = (const float*)d_in[i];
        else if (in_sizes[i] == 16 * 20 * 20 * 255) p5 = (const float*)d_in[i];
    }
    float* out = (float*)d_out;

    decode_kernel<<<(NB * 8400) / K1_CELLS, K1_THREADS>>>(p3, p4, p5);  // 8400 blocks
    topk_nms_kernel<<<NB * NCLS, 256>>>();                              // 1280 blocks
    final_kernel<<<NB, 256>>>(out);                                     // 16 blocks
}

// round 15
// speedup vs baseline: 1.8697x; 1.1378x over previous
#include <cuda_runtime.h>
#include <stdint.h>
#include <math.h>

// ---------------------------------------------------------------------------
// Problem constants
// ---------------------------------------------------------------------------
#define NB      16       // batch
#define NCLS    80       // classes
#define NANCH   25200    // 80*80*3 + 40*40*3 + 20*20*3
#define TOPK    128      // NMS_TOPK
#define MAXOUT  100
#define SCORE_THR 0.25f
#define IOU_THR   0.45f

#define K1_CELLS   16
#define K1_THREADS 128
#define CAND_MAX   2048
#define FINAL_MAX  512

// ---------------------------------------------------------------------------
// Scratch (static __device__ arrays — no allocation allowed)
// ---------------------------------------------------------------------------
__device__ float g_scores[(size_t)NB * NCLS * NANCH];      // (B, C, N) class-major, 129 MB
__device__ float g_boxes[(size_t)NB * NANCH * 4];          // (B, N, 4)
__device__ float g_cls_scores[NB * NCLS * MAXOUT];         // per-class NMS scores (-1 = invalid)
__device__ float g_cls_boxes[NB * NCLS * MAXOUT * 4];      // per-class NMS boxes

__constant__ float c_anchor_w[9] = {10.f, 16.f, 33.f, 30.f, 62.f, 59.f, 116.f, 156.f, 373.f};
__constant__ float c_anchor_h[9] = {13.f, 30.f, 23.f, 61.f, 45.f, 119.f, 90.f, 198.f, 326.f};

__device__ __forceinline__ float sigm(float x) {
    return 1.0f / (1.0f + expf(-x));
}

__device__ __forceinline__ unsigned long long mkkey(unsigned ub, int n) {
    return ((unsigned long long)ub << 32) | (unsigned)(0x00FFFFFF - n);
}

// ---------------------------------------------------------------------------
// K1: decode + score transpose (round-4 structure, measured ~70us)
// ---------------------------------------------------------------------------
__global__ __launch_bounds__(K1_THREADS) void decode_kernel(
    const float* __restrict__ p3, const float* __restrict__ p4, const float* __restrict__ p5)
{
    __shared__ float s_in[K1_CELLS * 255];
    __shared__ float s_obj[K1_CELLS * 3];

    const int tid = threadIdx.x;
    int cell0 = blockIdx.x * K1_CELLS;
    int b  = cell0 / 8400;
    int r0 = cell0 - b * 8400;

    const float* src; int W; float strd; int abase; int n0; int hw0;
    if (r0 < 6400)      { hw0 = r0;        W = 80; strd = 8.f;  abase = 0; src = p3 + ((size_t)b * 6400 + hw0) * 255; n0 = hw0 * 3; }
    else if (r0 < 8000) { hw0 = r0 - 6400; W = 40; strd = 16.f; abase = 3; src = p4 + ((size_t)b * 1600 + hw0) * 255; n0 = 19200 + hw0 * 3; }
    else                { hw0 = r0 - 8000; W = 20; strd = 32.f; abase = 6; src = p5 + ((size_t)b *  400 + hw0) * 255; n0 = 24000 + hw0 * 3; }

    #pragma unroll 4
    for (int i = tid; i < K1_CELLS * 255; i += K1_THREADS) s_in[i] = src[i];
    __syncthreads();

    if (tid < K1_CELLS * 3) {
        int cl = tid / 3;
        int a  = tid - cl * 3;
        int hw = hw0 + cl;
        int y  = hw / W;
        int x  = hw - y * W;
        const float* q = s_in + tid * 85;

        float cx = (sigm(q[0]) + (float)x) * strd;
        float cy = (sigm(q[1]) + (float)y) * strd;
        float w  = expf(q[2]) * c_anchor_w[abase + a];
        float h  = expf(q[3]) * c_anchor_h[abase + a];

        float* bo = g_boxes + ((size_t)b * NANCH + n0 + tid) * 4;
        bo[0] = cx - w * 0.5f;
        bo[1] = cy - h * 0.5f;
        bo[2] = cx + w * 0.5f;
        bo[3] = cy + h * 0.5f;

        s_obj[tid] = sigm(q[4]);
    }
    __syncthreads();

    const int NA = K1_CELLS * 3;               // 48
    #pragma unroll 5
    for (int w = 0; w < (NA * NCLS) / K1_THREADS; ++w) {   // 30 iterations
        int idx = w * K1_THREADS + tid;
        int c = idx / NA;
        int j = idx - c * NA;
        float v = s_obj[j] * sigm(s_in[j * 85 + 5 + c]);
        g_scores[((size_t)b * NCLS + c) * NANCH + n0 + j] = v;
    }
}

// ---------------------------------------------------------------------------
// K2: per (b, class): exact top-128 + NMS.
// ONE float4 scan appends scores > 0.5 (~1100/row, cheap single-counter
// atomics). Exact threshold found by histogramming ONLY the collected keys.
// Exact fallbacks re-scan when < 128 collected or overflow (data: ~never).
// Histogram region aliased with post-threshold buffers (smem ~33.5KB).
// ---------------------------------------------------------------------------
__global__ __launch_bounds__(256) void topk_nms_kernel()
{
    const int task = blockIdx.x;
    const int b = task / NCLS;
    const int c = task - b * NCLS;
    const int tid = threadIdx.x;

    const float* __restrict__ srow = g_scores + ((size_t)b * NCLS + c) * NANCH;
    const float4* __restrict__ srow4 = (const float4*)srow;   // rows are 16B aligned

    __shared__ unsigned long long s_cand[CAND_MAX];           // 16 KB raw candidates
    __shared__ __align__(8) unsigned char u_raw[16384];       // 16 KB union region
    unsigned* hist = (unsigned*)u_raw;                        // [phase 1] 4096 buckets
    unsigned long long* s_fin = (unsigned long long*)u_raw;   // [phase 2] 512 keys
    float* s_bx1 = (float*)(u_raw + 4096);                    // [phase 2] boxes
    float* s_by1 = s_bx1 + TOPK;
    float* s_bx2 = s_by1 + TOPK;
    float* s_by2 = s_bx2 + TOPK;
    float* s_area = s_by2 + TOPK;
    float* s_score = s_area + TOPK;                           // ends at 7168
    unsigned (*s_sup)[4] = (unsigned(*)[4])(u_raw + 7168);    // 2 KB, ends at 9216

    __shared__ unsigned s_csum[256];
    __shared__ unsigned s_T, s_cnt, s_acc, s_fcnt;
    __shared__ unsigned s_keep[4];
    __shared__ unsigned s_vball[4];

    for (int i = tid; i < 4096; i += 256) hist[i] = 0;
    if (tid == 0) { s_cnt = 0; s_fcnt = 0; }
    __syncthreads();

    // --- single dense scan (float4): append scores > 0.5 ---
    for (int i = tid; i < NANCH / 4; i += 256) {              // 6300 float4s, ~25 iters
        float4 v = srow4[i];
        int n = i * 4;
        if (v.x > 0.5f) { unsigned p = atomicAdd(&s_cnt, 1u); if (p < CAND_MAX) s_cand[p] = mkkey(__float_as_uint(v.x), n); }
        if (v.y > 0.5f) { unsigned p = atomicAdd(&s_cnt, 1u); if (p < CAND_MAX) s_cand[p] = mkkey(__float_as_uint(v.y), n + 1); }
        if (v.z > 0.5f) { unsigned p = atomicAdd(&s_cnt, 1u); if (p < CAND_MAX) s_cand[p] = mkkey(__float_as_uint(v.z), n + 2); }
        if (v.w > 0.5f) { unsigned p = atomicAdd(&s_cnt, 1u); if (p < CAND_MAX) s_cand[p] = mkkey(__float_as_uint(v.w), n + 3); }
    }
    __syncthreads();

    const unsigned n_big = s_cnt;
    const bool fast = (n_big >= TOPK) && (n_big <= CAND_MAX);

    // --- histogram: collected keys (fast) or full row > 0.25 (fallback) ---
    if (fast) {
        for (int i = tid; i < (int)n_big; i += 256) {
            unsigned bk = min(((unsigned)(s_cand[i] >> 32) - 0x3E800000u) >> 12, 4095u);
            atomicAdd(&hist[bk], 1u);
        }
    } else {
        for (int i = tid; i < NANCH / 4; i += 256) {
            float4 v = srow4[i];
            float vs[4] = {v.x, v.y, v.z, v.w};
            #pragma unroll
            for (int q = 0; q < 4; ++q) {
                if (vs[q] > SCORE_THR) {
                    unsigned bk = min((__float_as_uint(vs[q]) - 0x3E800000u) >> 12, 4095u);
                    atomicAdd(&hist[bk], 1u);
                }
            }
        }
    }
    __syncthreads();

    // --- threshold bucket T: first suffix count >= 128 ---
    unsigned sum = 0;
    #pragma unroll
    for (int k = 0; k < 16; ++k) sum += hist[tid * 16 + k];
    s_csum[tid] = sum;
    __syncthreads();

    if (tid == 0) {
        unsigned acc = 0;
        int ch;
        for (ch = 255; ch >= 0; --ch) {
            if (acc + s_csum[ch] >= TOPK) break;
            acc += s_csum[ch];
        }
        unsigned T = 0;
        if (ch >= 0) {
            for (int q = ch * 16 + 15; q >= ch * 16; --q) {
                acc += hist[q];
                if (acc >= TOPK) { T = (unsigned)q; break; }
            }
        }
        s_T = T;
        s_acc = acc;
    }
    __syncthreads();

    const unsigned T = s_T;
    const unsigned acc = s_acc;
    const bool doFilter = fast && (acc <= FINAL_MAX);

    if (doFilter) {
        // filter ~1100 -> ~acc (<=512) keys with bucket >= T into s_fin (aliased, hist dead)
        for (int i = tid; i < (int)n_big; i += 256) {
            unsigned long long key = s_cand[i];
            unsigned bk = min(((unsigned)(key >> 32) - 0x3E800000u) >> 12, 4095u);
            if (bk >= T) {
                unsigned p = atomicAdd(&s_fcnt, 1u);
                s_fin[p] = key;                // p < acc <= FINAL_MAX guaranteed
            }
        }
    } else if (!fast) {
        // exact fallback: re-scan row, collect bucket >= T
        for (int i = tid; i < NANCH / 4; i += 256) {
            float4 v = srow4[i];
            float vs[4] = {v.x, v.y, v.z, v.w};
            #pragma unroll
            for (int q = 0; q < 4; ++q) {
                if (vs[q] > SCORE_THR) {
                    unsigned ub = __float_as_uint(vs[q]);
                    unsigned bk = min((ub - 0x3E800000u) >> 12, 4095u);
                    if (bk >= T) {
                        unsigned p = atomicAdd(&s_fcnt, 1u);
                        if (p < CAND_MAX) s_cand[p] = mkkey(ub, i * 4 + q);
                    }
                }
            }
        }
    }
    // fast && acc > FINAL_MAX: sort all n_big keys in s_cand directly (exact superset)
    __syncthreads();

    unsigned long long* buf = doFilter ? s_fin : s_cand;
    int ccnt = doFilter ? (int)s_fcnt
             : (fast ? (int)n_big : (int)min(s_fcnt, (unsigned)CAND_MAX));
    int P = TOPK;
    while (P < ccnt) P <<= 1;                  // pow2; <= 512 (filter) or <= 2048
    for (int i = ccnt + tid; i < P; i += 256) buf[i] = 0ull;
    __syncthreads();

    // --- bitonic sort P keys descending (P typically 256) ---
    for (int k = 2; k <= P; k <<= 1) {
        for (int j = k >> 1; j > 0; j >>= 1) {
            for (int i = tid; i < P; i += 256) {
                int l = i ^ j;
                if (l > i) {
                    unsigned long long a  = buf[i];
                    unsigned long long bb = buf[l];
                    bool desc = ((i & k) == 0);
                    if ((a < bb) == desc) { buf[i] = bb; buf[l] = a; }
                }
            }
            __syncthreads();
        }
    }

    // --- gather top-128 candidates ---
    if (tid < MAXOUT) g_cls_scores[task * MAXOUT + tid] = -1.0f;   // default invalid

    if (tid < TOPK) {
        unsigned long long key = buf[tid];
        float s = __uint_as_float((unsigned)(key >> 32));
        int n = 0x00FFFFFF - (int)(unsigned)(key & 0xFFFFFFFFull);
        if (!(s > 0.f)) n = 0;     // padding slot: any in-range box, never used
        s_score[tid] = s;
        const float* bp = g_boxes + ((size_t)b * NANCH + n) * 4;
        float x1 = bp[0], y1 = bp[1], x2 = bp[2], y2 = bp[3];
        s_bx1[tid] = x1; s_by1[tid] = y1; s_bx2[tid] = x2; s_by2[tid] = y2;
        s_area[tid] = (x2 - x1) * (y2 - y1);
    }
    __syncthreads();

    // --- suppression bitmask: s_sup[i][w] bit t set iff j=32w+t > i and iou > thr ---
    for (int wi = tid; wi < TOPK * 4; wi += 256) {
        int i = wi >> 2;
        int w = wi & 3;
        float ax1 = s_bx1[i], ay1 = s_by1[i], ax2 = s_bx2[i], ay2 = s_by2[i], aa = s_area[i];
        unsigned m = 0;
        #pragma unroll 4
        for (int tt = 0; tt < 32; ++tt) {
            int j = (w << 5) + tt;
            if (j > i) {
                float iw = fmaxf(fminf(ax2, s_bx2[j]) - fmaxf(ax1, s_bx1[j]), 0.f);
                float ih = fmaxf(fminf(ay2, s_by2[j]) - fmaxf(ay1, s_by1[j]), 0.f);
                float inter = iw * ih;
                float iou = inter / (aa + s_area[j] - inter + 1e-9f);
                if (iou > IOU_THR) m |= (1u << tt);
            }
        }
        s_sup[i][w] = m;
    }
    __syncthreads();

    // --- sequential NMS scan on 128-bit bitmask ---
    if (tid == 0) {
        unsigned k0 = 0xFFFFFFFFu, k1 = 0xFFFFFFFFu, k2 = 0xFFFFFFFFu, k3 = 0xFFFFFFFFu;
        for (int i = 0; i < TOPK; ++i) {
            unsigned kw = (i < 32) ? k0 : (i < 64) ? k1 : (i < 96) ? k2 : k3;
            if (((kw >> (i & 31)) & 1u) && (s_score[i] > 0.f)) {
                k0 &= ~s_sup[i][0]; k1 &= ~s_sup[i][1]; k2 &= ~s_sup[i][2]; k3 &= ~s_sup[i][3];
            }
        }
        s_keep[0] = k0; s_keep[1] = k1; s_keep[2] = k2; s_keep[3] = k3;
    }
    __syncthreads();

    // --- compact valid survivors in order -> per-class top-100 ---
    bool valid = false;
    if (tid < TOPK) {
        valid = (((s_keep[tid >> 5] >> (tid & 31)) & 1u) != 0) && (s_score[tid] > 0.f);
        unsigned bal = __ballot_sync(0xFFFFFFFFu, valid);
        if ((tid & 31) == 0) s_vball[tid >> 5] = bal;
    }
    __syncthreads();

    if (tid < TOPK && valid) {
        int w = tid >> 5;
        int pos = __popc(s_vball[w] & ((1u << (tid & 31)) - 1u));
        #pragma unroll
        for (int q = 0; q < 4; ++q) if (q < w) pos += __popc(s_vball[q]);
        if (pos < MAXOUT) {
            size_t o = (size_t)task * MAXOUT + pos;
            g_cls_scores[o] = s_score[tid];
            float* ob = g_cls_boxes + o * 4;
            ob[0] = s_bx1[tid]; ob[1] = s_by1[tid]; ob[2] = s_bx2[tid]; ob[3] = s_by2[tid];
        }
    }
}

// ---------------------------------------------------------------------------
// K3: per-image top-100 via histogram threshold (round-11, measured 16.6us)
// ---------------------------------------------------------------------------
#define F_CAND 1024
__global__ __launch_bounds__(256) void final_kernel(float* __restrict__ out)
{
    const int b = blockIdx.x;
    const int tid = threadIdx.x;
    const float* __restrict__ scores = g_cls_scores + b * NCLS * MAXOUT;

    __shared__ unsigned hist[4096];
    __shared__ unsigned long long s_cand[F_CAND];
    __shared__ unsigned s_csum[256];
    __shared__ unsigned s_T, s_cnt, s_total;

    for (int i = tid; i < 4096; i += 256) hist[i] = 0;
    __syncthreads();

    for (int i = tid; i < NCLS * MAXOUT; i += 256) {
        float s = scores[i];
        if (s > 0.f) {
            unsigned bk = min((__float_as_uint(s) - 0x3E800000u) >> 12, 4095u);
            atomicAdd(&hist[bk], 1u);
        }
    }
    __syncthreads();

    unsigned sum = 0;
    #pragma unroll
    for (int k = 0; k < 16; ++k) sum += hist[tid * 16 + k];
    s_csum[tid] = sum;
    __syncthreads();

    if (tid == 0) {
        unsigned total = 0;
        for (int q = 0; q < 256; ++q) total += s_csum[q];
        unsigned acc = 0;
        int ch;
        for (ch = 255; ch >= 0; --ch) {
            if (acc + s_csum[ch] >= MAXOUT) break;
            acc += s_csum[ch];
        }
        unsigned T = 0;
        if (ch >= 0) {
            for (int q = ch * 16 + 15; q >= ch * 16; --q) {
                acc += hist[q];
                if (acc >= MAXOUT) { T = (unsigned)q; break; }
            }
        }
        s_T = T;
        s_cnt = 0;
        s_total = total;
    }
    __syncthreads();

    unsigned T = s_T;
    for (int i = tid; i < NCLS * MAXOUT; i += 256) {
        float s = scores[i];
        if (s > 0.f) {
            unsigned ub = __float_as_uint(s);
            unsigned bk = min((ub - 0x3E800000u) >> 12, 4095u);
            if (bk >= T) {
                unsigned p = atomicAdd(&s_cnt, 1u);
                if (p < F_CAND)
                    s_cand[p] = ((unsigned long long)ub << 32) | (unsigned)(0x1FFFu - i);
            }
        }
    }
    __syncthreads();

    int ccnt = (int)min(s_cnt, (unsigned)F_CAND);
    int P = 128;
    while (P < ccnt) P <<= 1;
    for (int i = ccnt + tid; i < P; i += 256) s_cand[i] = 0ull;
    __syncthreads();

    for (int k = 2; k <= P; k <<= 1) {
        for (int j = k >> 1; j > 0; j >>= 1) {
            for (int i = tid; i < P; i += 256) {
                int l = i ^ j;
                if (l > i) {
                    unsigned long long a  = s_cand[i];
                    unsigned long long bb = s_cand[l];
                    bool desc = ((i & k) == 0);
                    if ((a < bb) == desc) { s_cand[i] = bb; s_cand[l] = a; }
                }
            }
            __syncthreads();
        }
    }

    if (tid < MAXOUT) {
        unsigned long long key = s_cand[tid];
        bool val = key != 0ull;
        float* ob = out + ((size_t)b * MAXOUT + tid) * 4;
        if (val) {
            int flat = 0x1FFF - (int)(unsigned)(key & 0xFFFFFFFFull);
            float s = __uint_as_float((unsigned)(key >> 32));
            const float* bp = g_cls_boxes + ((size_t)b * NCLS * MAXOUT + flat) * 4;
            ob[0] = bp[0]; ob[1] = bp[1]; ob[2] = bp[2]; ob[3] = bp[3];
            out[NB * MAXOUT * 4 + b * MAXOUT + tid] = s;
            out[NB * MAXOUT * 5 + b * MAXOUT + tid] = (float)(flat / MAXOUT);
        } else {
            ob[0] = 0.f; ob[1] = 0.f; ob[2] = 0.f; ob[3] = 0.f;
            out[NB * MAXOUT * 4 + b * MAXOUT + tid] = 0.f;
            out[NB * MAXOUT * 5 + b * MAXOUT + tid] = 0.f;
        }
    }
    if (tid == 0)
        out[NB * MAXOUT * 6 + b] = (float)min(s_total, (unsigned)MAXOUT);
}

// ---------------------------------------------------------------------------
// Entry point
// ---------------------------------------------------------------------------
extern "C" void kernel_launch(void* const* d_in, const int* in_sizes, int n_in,
                              void* d_out, int out_size)
{
    const float* p3 = nullptr; const float* p4 = nullptr; const float* p5 = nullptr;
    for (int i = 0; i < n_in; ++i) {
        if      (in_sizes[i] == 16 * 80 * 80 * 255) p3 = (const float*)d_in[i];
        else if (in_sizes[i] == 16 * 40 * 40 * 255) p4 = (const float*)d_in[i];
        else if (in_sizes[i] == 16 * 20 * 20 * 255) p5 = (const float*)d_in[i];
    }
    float* out = (float*)d_out;

    decode_kernel<<<(NB * 8400) / K1_CELLS, K1_THREADS>>>(p3, p4, p5);  // 8400 blocks
    topk_nms_kernel<<<NB * NCLS, 256>>>();                              // 1280 blocks
    final_kernel<<<NB, 256>>>(out);                                     // 16 blocks
}